// round 7
// baseline (speedup 1.0000x reference)
#include <cuda_runtime.h>
#include <math.h>
#include <stdint.h>

// ---------------- problem constants ----------------
#define BB    128
#define NI    8192
#define NW    16384
#define EE    64
#define KP    4
#define TWOE  128

#define OUT_RATING  0
#define OUT_TEXT    (128*8192)
#define OUT_CFMU    (OUT_TEXT + 128*16384)
#define OUT_CFLV    (OUT_CFMU + 4*128*64)
#define OUT_TXMU    (OUT_CFLV + 4*128*64)
#define OUT_TXLV    (OUT_TXMU + 4*128*64)

#define HSPLIT 64

// hpart mma tile config (128x128)
#define BLKK   32
#define S_LD   36
#define BUF_B  (128*S_LD*4)
#define SMEM_GEMM (4*BUF_B)

// adjacency mma tile config (128x64, 3 CTAs/SM)
#define ADJ_SMEM ((2*128*S_LD + 2*64*S_LD)*4)     // 55296 bytes
#define ASPLIT 8

// ---------------- scratch ----------------
__device__ float g_protos_cf[KP*EE];
__device__ float g_protos_tx[KP*EE];
__device__ float g_items_cf[NI*EE];
__device__ float g_items_tx[NW*EE];
__device__ float g_cates_cf[NI*KP];
__device__ float g_cates_tx[NW*KP];
__device__ float g_ctT_cf[KP*NI];
__device__ float g_ctT_tx[KP*NW];
__device__ float g_rnp_cf[KP*BB*8];
__device__ float g_rnp_tx[KP*BB*8];
__device__ float g_P1T[TWOE*NI];
__device__ float g_MT [TWOE*NI];
__device__ float g_bigpart[8*NI*TWOE];
__device__ float g_part_cf[HSPLIT*512*TWOE];
__device__ float g_part_tx[HSPLIT*512*TWOE];

// ---------------- k0: normalize prototypes ----------------
__global__ void proto_norm_k(const float* __restrict__ cfp, const float* __restrict__ txp) {
    int tid = threadIdx.x;
    int w = tid >> 5, lane = tid & 31;
    const float* src = (w < 4) ? cfp : txp;
    float* dst = (w < 4) ? g_protos_cf : g_protos_tx;
    int row = w & 3;
    float v0 = src[row*EE + lane];
    float v1 = src[row*EE + 32 + lane];
    float s = v0*v0 + v1*v1;
    #pragma unroll
    for (int off = 16; off; off >>= 1) s += __shfl_xor_sync(0xffffffffu, s, off);
    float inv = 1.0f / fmaxf(sqrtf(s), 1e-12f);
    dst[row*EE + lane]      = v0 * inv;
    dst[row*EE + 32 + lane] = v1 * inv;
}

// ---------------- k1: item norm + cates softmax (+ transposed) ----------------
__global__ void __launch_bounds__(256) items_cates_k(
        const float* __restrict__ emb, const float* __restrict__ protos_g,
        float* __restrict__ items_out, float* __restrict__ cates_out,
        float* __restrict__ catesT_out, int N)
{
    __shared__ float ps[KP*EE];
    int tid = threadIdx.x;
    ps[tid] = protos_g[tid];
    __syncthreads();
    int w = tid >> 5, lane = tid & 31;
    int n = blockIdx.x * 8 + w;
    if (n >= N) return;
    float v0 = emb[n*EE + lane];
    float v1 = emb[n*EE + 32 + lane];
    float s = v0*v0 + v1*v1;
    #pragma unroll
    for (int off = 16; off; off >>= 1) s += __shfl_xor_sync(0xffffffffu, s, off);
    float inv = 1.0f / fmaxf(sqrtf(s), 1e-12f);
    float h0 = v0 * inv, h1 = v1 * inv;
    items_out[n*EE + lane]      = h0;
    items_out[n*EE + 32 + lane] = h1;
    float d[KP];
    #pragma unroll
    for (int k = 0; k < KP; k++) {
        float dk = h0 * ps[k*EE + lane] + h1 * ps[k*EE + 32 + lane];
        #pragma unroll
        for (int off = 16; off; off >>= 1) dk += __shfl_xor_sync(0xffffffffu, dk, off);
        d[k] = dk;
    }
    if (lane == 0) {
        float m = fmaxf(fmaxf(d[0], d[1]), fmaxf(d[2], d[3]));
        float e0 = __expf(d[0]-m), e1 = __expf(d[1]-m), e2 = __expf(d[2]-m), e3 = __expf(d[3]-m);
        float is = 1.0f / (e0+e1+e2+e3);
        float c0 = e0*is, c1 = e1*is, c2 = e2*is, c3 = e3*is;
        *(float4*)&cates_out[n*KP] = make_float4(c0, c1, c2, c3);
        catesT_out[0*N + n] = c0;
        catesT_out[1*N + n] = c1;
        catesT_out[2*N + n] = c2;
        catesT_out[3*N + n] = c3;
    }
}

// ---------------- k2: rnorm partials ----------------
__global__ void __launch_bounds__(256) rnormp_k(
        const float* __restrict__ x, const float* __restrict__ cates,
        float* __restrict__ rnp, int N)
{
    __shared__ float red[8][KP];
    int b = blockIdx.x, chunk = blockIdx.y, tid = threadIdx.x;
    int n0 = chunk * (N >> 3), n1 = n0 + (N >> 3);
    float s0=0.f, s1=0.f, s2=0.f, s3=0.f;
    const float* xr = x + (size_t)b * N;
    for (int n = n0 + tid; n < n1; n += 256) {
        float xv = xr[n];
        float4 c = *(const float4*)&cates[n*KP];
        float t0 = xv*c.x, t1 = xv*c.y, t2 = xv*c.z, t3 = xv*c.w;
        s0 += t0*t0; s1 += t1*t1; s2 += t2*t2; s3 += t3*t3;
    }
    #pragma unroll
    for (int off = 16; off; off >>= 1) {
        s0 += __shfl_xor_sync(0xffffffffu, s0, off);
        s1 += __shfl_xor_sync(0xffffffffu, s1, off);
        s2 += __shfl_xor_sync(0xffffffffu, s2, off);
        s3 += __shfl_xor_sync(0xffffffffu, s3, off);
    }
    int w = tid >> 5;
    if ((tid & 31) == 0) { red[w][0]=s0; red[w][1]=s1; red[w][2]=s2; red[w][3]=s3; }
    __syncthreads();
    if (tid < KP) {
        float t = 0.f;
        #pragma unroll
        for (int i = 0; i < 8; i++) t += red[i][tid];
        rnp[(tid*BB + b)*8 + chunk] = t;
    }
}

// ---------------- TF32 / mma helpers ----------------
__device__ __forceinline__ uint32_t f2tf(float f) {
    uint32_t r;
    asm("cvt.rna.tf32.f32 %0, %1;" : "=r"(r) : "f"(f));
    return r;
}
__device__ __forceinline__ void mma_tf32(float c[4], const uint32_t a[4],
                                         uint32_t b0, uint32_t b1) {
    asm volatile(
        "mma.sync.aligned.m16n8k8.row.col.f32.tf32.tf32.f32 "
        "{%0,%1,%2,%3}, {%4,%5,%6,%7}, {%8,%9}, {%0,%1,%2,%3};"
        : "+f"(c[0]), "+f"(c[1]), "+f"(c[2]), "+f"(c[3])
        : "r"(a[0]), "r"(a[1]), "r"(a[2]), "r"(a[3]), "r"(b0), "r"(b1));
}
__device__ __forceinline__ void ldsm4(uint32_t& r0, uint32_t& r1,
                                      uint32_t& r2, uint32_t& r3, uint32_t addr) {
    asm volatile("ldmatrix.sync.aligned.m8n8.x4.shared.b16 {%0,%1,%2,%3}, [%4];"
                 : "=r"(r0), "=r"(r1), "=r"(r2), "=r"(r3) : "r"(addr));
}

// ---------------- adjacency TF32 GEMM: 128(M)x64(N) tile, 3 CTAs/SM -------------
// A row-major [m][Ktot]; B rows [o][Ktot]; out part[(bz*NI + m)*TWOE + o]
// grid: (2 n-blocks [x, fastest -> L2 A-tile sharing], 64 m-tiles [y], ASPLIT [z])
__global__ void __launch_bounds__(256, 3) adj_gemm_k(
        const float* __restrict__ A, const float* __restrict__ B,
        float* __restrict__ part, int Ktot, int Ksplit)
{
    extern __shared__ uint32_t usmem[];
    uint32_t* Asm = usmem;                       // [2][128][S_LD]
    uint32_t* Bsm = usmem + 2*128*S_LD;          // [2][64][S_LD]
    int tid = threadIdx.x;
    int lane = tid & 31, w = tid >> 5;
    int wm = w & 3, wn = w >> 2;                 // 4 warps M, 2 warps N
    int lr = lane >> 2, lc = lane & 3;
    int n0 = blockIdx.x * 64;
    int m0 = blockIdx.y * 128;
    int kc0 = blockIdx.z * Ksplit;
    int niter = Ksplit / BLKK;

    uint32_t as_base = (uint32_t)__cvta_generic_to_shared(Asm);
    uint32_t bs_base = (uint32_t)__cvta_generic_to_shared(Bsm);
    int sel = lane >> 3, lr8 = lane & 7;
    uint32_t a_off = ((wm*32 + (sel&1)*8 + lr8)*S_LD + (sel>>1)*4) * 4;
    uint32_t b_off = ((wn*32 + (sel>>1)*8 + lr8)*S_LD + (sel&1)*4) * 4;

    float acc[2][4][4];
    #pragma unroll
    for (int mt = 0; mt < 2; mt++)
        #pragma unroll
        for (int nt = 0; nt < 4; nt++)
            #pragma unroll
            for (int i = 0; i < 4; i++) acc[mt][nt][i] = 0.f;

    float4 ra[4], rb[2];

    auto ldA = [&](int kc) {
        #pragma unroll
        for (int i = 0; i < 4; i++) {
            int idx = tid + i*256;
            int mm = idx >> 3, kk = (idx & 7) * 4;
            ra[i] = *(const float4*)(A + (size_t)(m0 + mm) * Ktot + kc + kk);
        }
    };
    auto stA = [&](int buf) {
        uint32_t* base = Asm + buf*128*S_LD;
        #pragma unroll
        for (int i = 0; i < 4; i++) {
            int idx = tid + i*256;
            int mm = idx >> 3, kk = (idx & 7) * 4;
            uint4 u;
            u.x = f2tf(ra[i].x); u.y = f2tf(ra[i].y);
            u.z = f2tf(ra[i].z); u.w = f2tf(ra[i].w);
            *(uint4*)(base + mm*S_LD + kk) = u;
        }
    };
    auto ldB = [&](int kc) {
        #pragma unroll
        for (int i = 0; i < 2; i++) {
            int idx = tid + i*256;
            int oo = idx >> 3, kk = (idx & 7) * 4;
            rb[i] = *(const float4*)(B + (size_t)(n0 + oo) * Ktot + kc + kk);
        }
    };
    auto stB = [&](int buf) {
        uint32_t* base = Bsm + buf*64*S_LD;
        #pragma unroll
        for (int i = 0; i < 2; i++) {
            int idx = tid + i*256;
            int oo = idx >> 3, kk = (idx & 7) * 4;
            uint4 u;
            u.x = f2tf(rb[i].x); u.y = f2tf(rb[i].y);
            u.z = f2tf(rb[i].z); u.w = f2tf(rb[i].w);
            *(uint4*)(base + oo*S_LD + kk) = u;
        }
    };
    auto compute = [&](int buf) {
        uint32_t abase = as_base + buf*(128*S_LD*4) + a_off;
        uint32_t bbase = bs_base + buf*(64*S_LD*4)  + b_off;
        #pragma unroll
        for (int ks = 0; ks < 4; ks++) {
            int k0b = ks * 8 * 4;
            uint32_t afr[2][4];
            #pragma unroll
            for (int mt = 0; mt < 2; mt++)
                ldsm4(afr[mt][0], afr[mt][1], afr[mt][2], afr[mt][3],
                      abase + mt*(16*S_LD*4) + k0b);
            #pragma unroll
            for (int np = 0; np < 2; np++) {
                uint32_t b0, b1, b2, b3;
                ldsm4(b0, b1, b2, b3, bbase + np*(16*S_LD*4) + k0b);
                mma_tf32(acc[0][2*np  ], afr[0], b0, b1);
                mma_tf32(acc[1][2*np  ], afr[1], b0, b1);
                mma_tf32(acc[0][2*np+1], afr[0], b2, b3);
                mma_tf32(acc[1][2*np+1], afr[1], b2, b3);
            }
        }
    };

    ldA(kc0); ldB(kc0); stA(0); stB(0);
    __syncthreads();
    for (int it = 0; it < niter; it++) {
        int cur = it & 1;
        if (it + 1 < niter) { ldA(kc0 + (it+1)*BLKK); ldB(kc0 + (it+1)*BLKK); }
        compute(cur);
        if (it + 1 < niter) { stA(1-cur); stB(1-cur); }
        __syncthreads();
    }

    #pragma unroll
    for (int mt = 0; mt < 2; mt++)
        #pragma unroll
        for (int nt = 0; nt < 4; nt++) {
            int row = m0 + wm*32 + mt*16 + lr;
            int col = n0 + wn*32 + nt*8 + lc*2;
            float* p = part + ((size_t)blockIdx.z * NI + row) * TWOE + col;
            *(float2*)p             = make_float2(acc[mt][nt][0], acc[mt][nt][1]);
            *(float2*)(p + 8*TWOE)  = make_float2(acc[mt][nt][2], acc[mt][nt][3]);
        }
}

// ---------------- hpart TF32 MMA GEMM (128x128 tile, amode=1) ----------------
__global__ void __launch_bounds__(256, 2) mma_gemm_k(
        const float* __restrict__ A, const float* __restrict__ ctT,
        const float* __restrict__ B, float* __restrict__ part,
        int Mrows, int Ktot, int Ksplit, int amode)
{
    extern __shared__ uint32_t usmem[];
    uint32_t* Asm = usmem;
    uint32_t* Bsm = usmem + 2*128*S_LD;
    int tid = threadIdx.x;
    int lane = tid & 31, w = tid >> 5;
    int wm = w & 3, wn = w >> 2;
    int lr = lane >> 2, lc = lane & 3;
    int m0 = blockIdx.x * 128;
    int kc0 = blockIdx.z * Ksplit;
    int niter = Ksplit / BLKK;
    const float* ctb = amode ? (ctT + (size_t)blockIdx.x * Ktot) : (const float*)0;

    uint32_t as_base = (uint32_t)__cvta_generic_to_shared(Asm);
    uint32_t bs_base = (uint32_t)__cvta_generic_to_shared(Bsm);
    int sel = lane >> 3, lr8 = lane & 7;
    uint32_t a_off = ((wm*32 + (sel&1)*8 + lr8)*S_LD + (sel>>1)*4) * 4;
    uint32_t b_off = ((wn*64 + (sel>>1)*8 + lr8)*S_LD + (sel&1)*4) * 4;

    float acc[2][8][4];
    #pragma unroll
    for (int mt = 0; mt < 2; mt++)
        #pragma unroll
        for (int nt = 0; nt < 8; nt++)
            #pragma unroll
            for (int i = 0; i < 4; i++) acc[mt][nt][i] = 0.f;

    float4 ra[4], rb[4];
    int bo = tid >> 1, bk0 = (tid & 1) * 16;

    auto ldA = [&](int kc) {
        #pragma unroll
        for (int i = 0; i < 4; i++) {
            int mm = (tid + i*256) >> 3;
            int kk = ((tid + i*256) & 7) * 4;
            if (amode == 0) {
                ra[i] = *(const float4*)(A + (size_t)(m0 + mm) * Ktot + kc + kk);
            } else {
                float4 v = *(const float4*)(A + (size_t)mm * Ktot + kc + kk);
                float4 c = *(const float4*)(ctb + kc + kk);
                v.x *= c.x; v.y *= c.y; v.z *= c.z; v.w *= c.w;
                ra[i] = v;
            }
        }
    };
    auto stA = [&](int buf) {
        uint32_t* base = Asm + buf*128*S_LD;
        #pragma unroll
        for (int i = 0; i < 4; i++) {
            int mm = (tid + i*256) >> 3;
            int kk = ((tid + i*256) & 7) * 4;
            uint4 u;
            u.x = f2tf(ra[i].x); u.y = f2tf(ra[i].y);
            u.z = f2tf(ra[i].z); u.w = f2tf(ra[i].w);
            *(uint4*)(base + mm*S_LD + kk) = u;
        }
    };
    auto ldB = [&](int kc) {
        #pragma unroll
        for (int i = 0; i < 4; i++)
            rb[i] = *(const float4*)(B + (size_t)bo * Ktot + kc + bk0 + i*4);
    };
    auto stB = [&](int buf) {
        uint32_t* base = Bsm + buf*128*S_LD + bo*S_LD + bk0;
        #pragma unroll
        for (int i = 0; i < 4; i++) {
            uint4 u;
            u.x = f2tf(rb[i].x); u.y = f2tf(rb[i].y);
            u.z = f2tf(rb[i].z); u.w = f2tf(rb[i].w);
            *(uint4*)(base + i*4) = u;
        }
    };
    auto compute = [&](int buf) {
        uint32_t abase = as_base + buf*BUF_B + a_off;
        uint32_t bbase = bs_base + buf*BUF_B + b_off;
        #pragma unroll
        for (int ks = 0; ks < 4; ks++) {
            int k0b = ks * 8 * 4;
            uint32_t afr[2][4];
            #pragma unroll
            for (int mt = 0; mt < 2; mt++)
                ldsm4(afr[mt][0], afr[mt][1], afr[mt][2], afr[mt][3],
                      abase + mt*(16*S_LD*4) + k0b);
            #pragma unroll
            for (int np = 0; np < 4; np++) {
                uint32_t b0, b1, b2, b3;
                ldsm4(b0, b1, b2, b3, bbase + np*(16*S_LD*4) + k0b);
                mma_tf32(acc[0][2*np  ], afr[0], b0, b1);
                mma_tf32(acc[1][2*np  ], afr[1], b0, b1);
                mma_tf32(acc[0][2*np+1], afr[0], b2, b3);
                mma_tf32(acc[1][2*np+1], afr[1], b2, b3);
            }
        }
    };

    ldA(kc0); ldB(kc0); stA(0); stB(0);
    __syncthreads();
    for (int it = 0; it < niter; it++) {
        int cur = it & 1;
        if (it + 1 < niter) { ldA(kc0 + (it+1)*BLKK); ldB(kc0 + (it+1)*BLKK); }
        compute(cur);
        if (it + 1 < niter) { stA(1-cur); stB(1-cur); }
        __syncthreads();
    }

    #pragma unroll
    for (int mt = 0; mt < 2; mt++)
        #pragma unroll
        for (int nt = 0; nt < 8; nt++) {
            int row = m0 + wm*32 + mt*16 + lr;
            int col = wn*64 + nt*8 + lc*2;
            float* p = part + ((size_t)blockIdx.z * Mrows + row) * TWOE + col;
            *(float2*)p             = make_float2(acc[mt][nt][0], acc[mt][nt][1]);
            *(float2*)(p + 8*TWOE)  = make_float2(acc[mt][nt][2], acc[mt][nt][3]);
        }
}

// ---------------- reduce split-K partials + transpose ----------------
__global__ void __launch_bounds__(256) reduceT_k(
        const float* __restrict__ part, const float* __restrict__ W,
        float* __restrict__ outT, int nsplit, int combine)
{
    __shared__ float t[64][65];
    int n0 = blockIdx.x * 64, o0 = blockIdx.y * 64;
    int c0 = threadIdx.x & 63, r4 = threadIdx.x >> 6;
    #pragma unroll
    for (int p = 0; p < 16; p++) {
        int nl = p*4 + r4;
        float s = 0.f;
        for (int z = 0; z < nsplit; z++)
            s += part[((size_t)z*NI + n0 + nl)*TWOE + o0 + c0];
        t[nl][c0] = s;
    }
    __syncthreads();
    #pragma unroll
    for (int p = 0; p < 16; p++) {
        int ol = p*4 + r4;
        float v = t[c0][ol];
        if (combine) v = 0.5f*(v + W[(size_t)(o0+ol)*NI + n0 + c0]);
        outT[(size_t)(o0+ol)*NI + n0 + c0] = v;
    }
}

// ---------------- finalize h -> mu / logvar ----------------
__global__ void __launch_bounds__(128) hfinal_k(
        const float* __restrict__ part, int nchunks,
        const float* __restrict__ rnp, const float* __restrict__ bias,
        float* __restrict__ out_mu, float* __restrict__ out_lv)
{
    __shared__ float sq[64];
    __shared__ float sinv, s_rn;
    int kb = blockIdx.x, o = threadIdx.x;
    if (o == 0) {
        float t = 0.f;
        #pragma unroll
        for (int c = 0; c < 8; c++) t += rnp[kb*8 + c];
        s_rn = 1.0f / fmaxf(sqrtf(t), 1e-12f);
    }
    float s = 0.f;
    for (int c = 0; c < nchunks; c++) s += part[(size_t)c*512*TWOE + (size_t)kb*TWOE + o];
    __syncthreads();
    float h = s * s_rn + bias[o];
    if (o < 64) sq[o] = h*h;
    __syncthreads();
    if (o == 0) {
        float t = 0.f;
        #pragma unroll
        for (int i = 0; i < 64; i++) t += sq[i];
        sinv = 1.0f / fmaxf(sqrtf(t), 1e-12f);
    }
    __syncthreads();
    if (o < 64) out_mu[(size_t)kb*EE + o] = h * sinv;
    else        out_lv[(size_t)kb*EE + (o-64)] = -h;
}

// ---------------- decoder ----------------
__global__ void __launch_bounds__(256) decoder_k(
        const float* __restrict__ items, const float* __restrict__ cates,
        const float* __restrict__ mu, float* __restrict__ out, int N)
{
    __shared__ float itemsT[64][68];
    __shared__ float mu_s[16][64][4];
    __shared__ float cs[64][4];
    int tid = threadIdx.x;
    int tx = tid & 15, ty = tid >> 4;
    int n0 = blockIdx.x * 64;
    int bt = blockIdx.y * 16;
    #pragma unroll
    for (int i = 0; i < 16; i++) {
        int idx = tid + i*256;
        int n = idx >> 6, e = idx & 63;
        itemsT[e][n] = items[(size_t)(n0+n)*EE + e];
    }
    #pragma unroll
    for (int i = 0; i < 16; i++) {
        int idx = tid + i*256;
        int kb = idx >> 6, e = idx & 63;
        int k = kb >> 4, b = kb & 15;
        mu_s[b][e][k] = mu[(size_t)(k*BB + bt + b)*EE + e];
    }
    {
        int n = tid >> 2, kk = tid & 3;
        cs[n][kk] = cates[(size_t)(n0+n)*KP + kk];
    }
    __syncthreads();

    float acc[4][KP];
    #pragma unroll
    for (int i = 0; i < 4; i++)
        #pragma unroll
        for (int k = 0; k < KP; k++) acc[i][k] = 0.f;

    #pragma unroll 4
    for (int e = 0; e < 64; e++) {
        float4 a = *(const float4*)&itemsT[e][tx*4];
        float4 mm = *(const float4*)&mu_s[ty][e][0];
        float aw[4] = {a.x, a.y, a.z, a.w};
        #pragma unroll
        for (int i = 0; i < 4; i++) {
            acc[i][0] += aw[i]*mm.x; acc[i][1] += aw[i]*mm.y;
            acc[i][2] += aw[i]*mm.z; acc[i][3] += aw[i]*mm.w;
        }
    }
    int b = bt + ty;
    #pragma unroll
    for (int i = 0; i < 4; i++) {
        int nl = tx*4 + i;
        float4 c = *(const float4*)&cs[nl][0];
        float p = __expf(acc[i][0])*c.x + __expf(acc[i][1])*c.y
                + __expf(acc[i][2])*c.z + __expf(acc[i][3])*c.w;
        out[(size_t)b*N + n0 + nl] = __logf(p);
    }
}

// ---------------- launch ----------------
extern "C" void kernel_launch(void* const* d_in, const int* in_sizes, int n_in,
                              void* d_out, int out_size)
{
    const float* x_cf    = (const float*)d_in[0];
    const float* x_tx    = (const float*)d_in[1];
    const float* adj     = (const float*)d_in[2];
    const float* cf_emb  = (const float*)d_in[3];
    const float* cf_prot = (const float*)d_in[4];
    const float* cf_W    = (const float*)d_in[5];
    const float* cf_b    = (const float*)d_in[6];
    const float* tx_emb  = (const float*)d_in[7];
    const float* tx_prot = (const float*)d_in[8];
    const float* tx_W    = (const float*)d_in[9];
    const float* tx_b    = (const float*)d_in[10];
    float* out = (float*)d_out;

    float *p_protos_cf, *p_protos_tx, *p_items_cf, *p_items_tx;
    float *p_cates_cf, *p_cates_tx, *p_ctT_cf, *p_ctT_tx, *p_rnp_cf, *p_rnp_tx;
    float *p_P1T, *p_MT, *p_big, *p_part_cf, *p_part_tx;
    cudaGetSymbolAddress((void**)&p_protos_cf, g_protos_cf);
    cudaGetSymbolAddress((void**)&p_protos_tx, g_protos_tx);
    cudaGetSymbolAddress((void**)&p_items_cf,  g_items_cf);
    cudaGetSymbolAddress((void**)&p_items_tx,  g_items_tx);
    cudaGetSymbolAddress((void**)&p_cates_cf,  g_cates_cf);
    cudaGetSymbolAddress((void**)&p_cates_tx,  g_cates_tx);
    cudaGetSymbolAddress((void**)&p_ctT_cf,    g_ctT_cf);
    cudaGetSymbolAddress((void**)&p_ctT_tx,    g_ctT_tx);
    cudaGetSymbolAddress((void**)&p_rnp_cf,    g_rnp_cf);
    cudaGetSymbolAddress((void**)&p_rnp_tx,    g_rnp_tx);
    cudaGetSymbolAddress((void**)&p_P1T,       g_P1T);
    cudaGetSymbolAddress((void**)&p_MT,        g_MT);
    cudaGetSymbolAddress((void**)&p_big,       g_bigpart);
    cudaGetSymbolAddress((void**)&p_part_cf,   g_part_cf);
    cudaGetSymbolAddress((void**)&p_part_tx,   g_part_tx);

    static cudaStream_t s_tx = nullptr, s_pre = nullptr;
    static cudaEvent_t ev_fork = nullptr, ev_tx = nullptr, ev_pre = nullptr;
    if (!s_tx) {
        cudaStreamCreateWithFlags(&s_tx,  cudaStreamNonBlocking);
        cudaStreamCreateWithFlags(&s_pre, cudaStreamNonBlocking);
        cudaEventCreateWithFlags(&ev_fork, cudaEventDisableTiming);
        cudaEventCreateWithFlags(&ev_tx,   cudaEventDisableTiming);
        cudaEventCreateWithFlags(&ev_pre,  cudaEventDisableTiming);
        cudaFuncSetAttribute(mma_gemm_k,
            cudaFuncAttributeMaxDynamicSharedMemorySize, SMEM_GEMM);
        cudaFuncSetAttribute(adj_gemm_k,
            cudaFuncAttributeMaxDynamicSharedMemorySize, ADJ_SMEM);
    }

    // ---- stem ----
    proto_norm_k<<<1, 256>>>(cf_prot, tx_prot);
    cudaEventRecord(ev_fork, 0);
    cudaStreamWaitEvent(s_tx,  ev_fork, 0);
    cudaStreamWaitEvent(s_pre, ev_fork, 0);

    // ---- text branch on s_tx ----
    items_cates_k<<<NW/8, 256, 0, s_tx>>>(tx_emb, p_protos_tx, p_items_tx, p_cates_tx, p_ctT_tx, NW);
    rnormp_k<<<dim3(BB, 8), 256, 0, s_tx>>>(x_tx, p_cates_tx, p_rnp_tx, NW);
    mma_gemm_k<<<dim3(4, 1, HSPLIT), 256, SMEM_GEMM, s_tx>>>(
        x_tx, p_ctT_tx, tx_W, p_part_tx, 512, NW, NW/HSPLIT, 1);
    hfinal_k<<<KP*BB, 128, 0, s_tx>>>(p_part_tx, HSPLIT, p_rnp_tx, tx_b,
                                      out + OUT_TXMU, out + OUT_TXLV);
    decoder_k<<<dim3(NW/64, BB/16), 256, 0, s_tx>>>(p_items_tx, p_cates_tx,
                                                    out + OUT_TXMU, out + OUT_TEXT, NW);
    cudaEventRecord(ev_tx, s_tx);

    // ---- cf prep on s_pre ----
    items_cates_k<<<NI/8, 256, 0, s_pre>>>(cf_emb, p_protos_cf, p_items_cf, p_cates_cf, p_ctT_cf, NI);
    rnormp_k<<<dim3(BB, 8), 256, 0, s_pre>>>(x_cf, p_cates_cf, p_rnp_cf, NI);
    cudaEventRecord(ev_pre, s_pre);

    // ---- adjacency chain ----
    // P1 = adj @ cf_W^T  -> P1T
    adj_gemm_k<<<dim3(2, NI/128, ASPLIT), 256, ADJ_SMEM>>>(adj, cf_W, p_big, NI, NI/ASPLIT);
    reduceT_k<<<dim3(NI/64, 2), 256>>>(p_big, nullptr, p_P1T, ASPLIT, 0);
    // P2 = adj @ P1 -> MT = 0.5*(P2T + W)
    adj_gemm_k<<<dim3(2, NI/128, ASPLIT), 256, ADJ_SMEM>>>(adj, p_P1T, p_big, NI, NI/ASPLIT);
    reduceT_k<<<dim3(NI/64, 2), 256>>>(p_big, cf_W, p_MT, ASPLIT, 1);

    // hpart_cf
    cudaStreamWaitEvent(0, ev_pre, 0);
    mma_gemm_k<<<dim3(4, 1, HSPLIT), 256, SMEM_GEMM>>>(
        x_cf, p_ctT_cf, p_MT, p_part_cf, 512, NI, NI/HSPLIT, 1);
    hfinal_k<<<KP*BB, 128>>>(p_part_cf, HSPLIT, p_rnp_cf, cf_b,
                             out + OUT_CFMU, out + OUT_CFLV);
    decoder_k<<<dim3(NI/64, BB/16), 256>>>(p_items_cf, p_cates_cf,
                                           out + OUT_CFMU, out + OUT_RATING, NI);

    cudaStreamWaitEvent(0, ev_tx, 0);
}

// round 8
// speedup vs baseline: 1.0706x; 1.0706x over previous
#include <cuda_runtime.h>
#include <math.h>
#include <stdint.h>

// ---------------- problem constants ----------------
#define BB    128
#define NI    8192
#define NW    16384
#define EE    64
#define KP    4
#define TWOE  128

#define OUT_RATING  0
#define OUT_TEXT    (128*8192)
#define OUT_CFMU    (OUT_TEXT + 128*16384)
#define OUT_CFLV    (OUT_CFMU + 4*128*64)
#define OUT_TXMU    (OUT_CFLV + 4*128*64)
#define OUT_TXLV    (OUT_TXMU + 4*128*64)

#define HSPLIT 64
#define ASPLIT 8

// mma tile config (128x128)
#define BLKK   32
#define S_LD   36
#define BUF_B  (128*S_LD*4)
#define SMEM_GEMM (4*BUF_B)

// ---------------- scratch ----------------
__device__ float g_protos_cf[KP*EE];
__device__ float g_protos_tx[KP*EE];
__device__ float g_items_cf[NI*EE];
__device__ float g_items_tx[NW*EE];
__device__ float g_cates_cf[NI*KP];
__device__ float g_cates_tx[NW*KP];
__device__ float g_ctT_cf[KP*NI];
__device__ float g_ctT_tx[KP*NW];
__device__ float g_rnp_cf[KP*BB*8];
__device__ float g_rnp_tx[KP*BB*8];
__device__ float g_P1T[TWOE*NI];
__device__ float g_MT [TWOE*NI];
__device__ float g_bigpart[8*NI*TWOE];
__device__ float g_part_cf[HSPLIT*512*TWOE];
__device__ float g_part_tx[HSPLIT*512*TWOE];

// ---------------- k0: normalize prototypes ----------------
__global__ void proto_norm_k(const float* __restrict__ cfp, const float* __restrict__ txp) {
    int tid = threadIdx.x;
    int w = tid >> 5, lane = tid & 31;
    const float* src = (w < 4) ? cfp : txp;
    float* dst = (w < 4) ? g_protos_cf : g_protos_tx;
    int row = w & 3;
    float v0 = src[row*EE + lane];
    float v1 = src[row*EE + 32 + lane];
    float s = v0*v0 + v1*v1;
    #pragma unroll
    for (int off = 16; off; off >>= 1) s += __shfl_xor_sync(0xffffffffu, s, off);
    float inv = 1.0f / fmaxf(sqrtf(s), 1e-12f);
    dst[row*EE + lane]      = v0 * inv;
    dst[row*EE + 32 + lane] = v1 * inv;
}

// ---------------- k1: item norm + cates softmax (+ transposed) ----------------
__global__ void __launch_bounds__(256) items_cates_k(
        const float* __restrict__ emb, const float* __restrict__ protos_g,
        float* __restrict__ items_out, float* __restrict__ cates_out,
        float* __restrict__ catesT_out, int N)
{
    __shared__ float ps[KP*EE];
    int tid = threadIdx.x;
    ps[tid] = protos_g[tid];
    __syncthreads();
    int w = tid >> 5, lane = tid & 31;
    int n = blockIdx.x * 8 + w;
    if (n >= N) return;
    float v0 = emb[n*EE + lane];
    float v1 = emb[n*EE + 32 + lane];
    float s = v0*v0 + v1*v1;
    #pragma unroll
    for (int off = 16; off; off >>= 1) s += __shfl_xor_sync(0xffffffffu, s, off);
    float inv = 1.0f / fmaxf(sqrtf(s), 1e-12f);
    float h0 = v0 * inv, h1 = v1 * inv;
    items_out[n*EE + lane]      = h0;
    items_out[n*EE + 32 + lane] = h1;
    float d[KP];
    #pragma unroll
    for (int k = 0; k < KP; k++) {
        float dk = h0 * ps[k*EE + lane] + h1 * ps[k*EE + 32 + lane];
        #pragma unroll
        for (int off = 16; off; off >>= 1) dk += __shfl_xor_sync(0xffffffffu, dk, off);
        d[k] = dk;
    }
    if (lane == 0) {
        float m = fmaxf(fmaxf(d[0], d[1]), fmaxf(d[2], d[3]));
        float e0 = __expf(d[0]-m), e1 = __expf(d[1]-m), e2 = __expf(d[2]-m), e3 = __expf(d[3]-m);
        float is = 1.0f / (e0+e1+e2+e3);
        float c0 = e0*is, c1 = e1*is, c2 = e2*is, c3 = e3*is;
        *(float4*)&cates_out[n*KP] = make_float4(c0, c1, c2, c3);
        catesT_out[0*N + n] = c0;
        catesT_out[1*N + n] = c1;
        catesT_out[2*N + n] = c2;
        catesT_out[3*N + n] = c3;
    }
}

// ---------------- k2: rnorm partials ----------------
__global__ void __launch_bounds__(256) rnormp_k(
        const float* __restrict__ x, const float* __restrict__ cates,
        float* __restrict__ rnp, int N)
{
    __shared__ float red[8][KP];
    int b = blockIdx.x, chunk = blockIdx.y, tid = threadIdx.x;
    int n0 = chunk * (N >> 3), n1 = n0 + (N >> 3);
    float s0=0.f, s1=0.f, s2=0.f, s3=0.f;
    const float* xr = x + (size_t)b * N;
    for (int n = n0 + tid; n < n1; n += 256) {
        float xv = xr[n];
        float4 c = *(const float4*)&cates[n*KP];
        float t0 = xv*c.x, t1 = xv*c.y, t2 = xv*c.z, t3 = xv*c.w;
        s0 += t0*t0; s1 += t1*t1; s2 += t2*t2; s3 += t3*t3;
    }
    #pragma unroll
    for (int off = 16; off; off >>= 1) {
        s0 += __shfl_xor_sync(0xffffffffu, s0, off);
        s1 += __shfl_xor_sync(0xffffffffu, s1, off);
        s2 += __shfl_xor_sync(0xffffffffu, s2, off);
        s3 += __shfl_xor_sync(0xffffffffu, s3, off);
    }
    int w = tid >> 5;
    if ((tid & 31) == 0) { red[w][0]=s0; red[w][1]=s1; red[w][2]=s2; red[w][3]=s3; }
    __syncthreads();
    if (tid < KP) {
        float t = 0.f;
        #pragma unroll
        for (int i = 0; i < 8; i++) t += red[i][tid];
        rnp[(tid*BB + b)*8 + chunk] = t;
    }
}

// ---------------- TF32 / mma helpers ----------------
__device__ __forceinline__ uint32_t f2tf(float f) {
    uint32_t r;
    asm("cvt.rna.tf32.f32 %0, %1;" : "=r"(r) : "f"(f));
    return r;
}
__device__ __forceinline__ void mma_tf32(float c[4], const uint32_t a[4],
                                         uint32_t b0, uint32_t b1) {
    asm volatile(
        "mma.sync.aligned.m16n8k8.row.col.f32.tf32.tf32.f32 "
        "{%0,%1,%2,%3}, {%4,%5,%6,%7}, {%8,%9}, {%0,%1,%2,%3};"
        : "+f"(c[0]), "+f"(c[1]), "+f"(c[2]), "+f"(c[3])
        : "r"(a[0]), "r"(a[1]), "r"(a[2]), "r"(a[3]), "r"(b0), "r"(b1));
}
__device__ __forceinline__ void ldsm4(uint32_t& r0, uint32_t& r1,
                                      uint32_t& r2, uint32_t& r3, uint32_t addr) {
    asm volatile("ldmatrix.sync.aligned.m8n8.x4.shared.b16 {%0,%1,%2,%3}, [%4];"
                 : "=r"(r0), "=r"(r1), "=r"(r2), "=r"(r3) : "r"(addr));
}

// ---------------- TF32 MMA GEMM, 128x128 tile, row-contiguous loaders ----------
// A: amode 0: row-major [m][Ktot] (m = bx*128 + local); amode 1: Y[m][n]=x[m][n]*ctT[bx][n]
// B: ALWAYS rows [o][Ktot] (128 rows)
// out: part[(bz*Mrows + row)*128 + o]
__global__ void __launch_bounds__(256, 2) mma_gemm_k(
        const float* __restrict__ A, const float* __restrict__ ctT,
        const float* __restrict__ B, float* __restrict__ part,
        int Mrows, int Ktot, int Ksplit, int amode)
{
    extern __shared__ uint32_t usmem[];
    uint32_t* Asm = usmem;
    uint32_t* Bsm = usmem + 2*128*S_LD;
    int tid = threadIdx.x;
    int lane = tid & 31, w = tid >> 5;
    int wm = w & 3, wn = w >> 2;
    int lr = lane >> 2, lc = lane & 3;
    int m0 = blockIdx.x * 128;
    int kc0 = blockIdx.z * Ksplit;
    int niter = Ksplit / BLKK;
    const float* ctb = amode ? (ctT + (size_t)blockIdx.x * Ktot) : (const float*)0;

    uint32_t as_base = (uint32_t)__cvta_generic_to_shared(Asm);
    uint32_t bs_base = (uint32_t)__cvta_generic_to_shared(Bsm);
    int sel = lane >> 3, lr8 = lane & 7;
    uint32_t a_off = ((wm*32 + (sel&1)*8 + lr8)*S_LD + (sel>>1)*4) * 4;
    uint32_t b_off = ((wn*64 + (sel>>1)*8 + lr8)*S_LD + (sel&1)*4) * 4;

    float acc[2][8][4];
    #pragma unroll
    for (int mt = 0; mt < 2; mt++)
        #pragma unroll
        for (int nt = 0; nt < 8; nt++)
            #pragma unroll
            for (int i = 0; i < 4; i++) acc[mt][nt][i] = 0.f;

    float4 ra[4], rb[4];

    auto ldA = [&](int kc) {
        #pragma unroll
        for (int i = 0; i < 4; i++) {
            int lin = tid + i*256;
            int mm = lin >> 3, kk = (lin & 7) * 4;
            if (amode == 0) {
                ra[i] = *(const float4*)(A + (size_t)(m0 + mm) * Ktot + kc + kk);
            } else {
                float4 v = *(const float4*)(A + (size_t)mm * Ktot + kc + kk);
                float4 c = *(const float4*)(ctb + kc + kk);
                v.x *= c.x; v.y *= c.y; v.z *= c.z; v.w *= c.w;
                ra[i] = v;
            }
        }
    };
    auto stA = [&](int buf) {
        uint32_t* base = Asm + buf*128*S_LD;
        #pragma unroll
        for (int i = 0; i < 4; i++) {
            int lin = tid + i*256;
            int mm = lin >> 3, kk = (lin & 7) * 4;
            uint4 u;
            u.x = f2tf(ra[i].x); u.y = f2tf(ra[i].y);
            u.z = f2tf(ra[i].z); u.w = f2tf(ra[i].w);
            *(uint4*)(base + mm*S_LD + kk) = u;
        }
    };
    // B loader: row-contiguous (nL=4 per LDG.128 instead of 16)
    auto ldB = [&](int kc) {
        #pragma unroll
        for (int i = 0; i < 4; i++) {
            int lin = tid + i*256;
            int oo = lin >> 3, kk = (lin & 7) * 4;
            rb[i] = *(const float4*)(B + (size_t)oo * Ktot + kc + kk);
        }
    };
    auto stB = [&](int buf) {
        uint32_t* base = Bsm + buf*128*S_LD;
        #pragma unroll
        for (int i = 0; i < 4; i++) {
            int lin = tid + i*256;
            int oo = lin >> 3, kk = (lin & 7) * 4;
            uint4 u;
            u.x = f2tf(rb[i].x); u.y = f2tf(rb[i].y);
            u.z = f2tf(rb[i].z); u.w = f2tf(rb[i].w);
            *(uint4*)(base + oo*S_LD + kk) = u;
        }
    };
    auto compute = [&](int buf) {
        uint32_t abase = as_base + buf*BUF_B + a_off;
        uint32_t bbase = bs_base + buf*BUF_B + b_off;
        #pragma unroll
        for (int ks = 0; ks < 4; ks++) {
            int k0b = ks * 8 * 4;
            uint32_t afr[2][4];
            #pragma unroll
            for (int mt = 0; mt < 2; mt++)
                ldsm4(afr[mt][0], afr[mt][1], afr[mt][2], afr[mt][3],
                      abase + mt*(16*S_LD*4) + k0b);
            #pragma unroll
            for (int np = 0; np < 4; np++) {
                uint32_t b0, b1, b2, b3;
                ldsm4(b0, b1, b2, b3, bbase + np*(16*S_LD*4) + k0b);
                mma_tf32(acc[0][2*np  ], afr[0], b0, b1);
                mma_tf32(acc[1][2*np  ], afr[1], b0, b1);
                mma_tf32(acc[0][2*np+1], afr[0], b2, b3);
                mma_tf32(acc[1][2*np+1], afr[1], b2, b3);
            }
        }
    };

    ldA(kc0); ldB(kc0); stA(0); stB(0);
    __syncthreads();
    for (int it = 0; it < niter; it++) {
        int cur = it & 1;
        if (it + 1 < niter) { ldA(kc0 + (it+1)*BLKK); ldB(kc0 + (it+1)*BLKK); }
        compute(cur);
        if (it + 1 < niter) { stA(1-cur); stB(1-cur); }
        __syncthreads();
    }

    #pragma unroll
    for (int mt = 0; mt < 2; mt++)
        #pragma unroll
        for (int nt = 0; nt < 8; nt++) {
            int row = m0 + wm*32 + mt*16 + lr;
            int col = wn*64 + nt*8 + lc*2;
            float* p = part + ((size_t)blockIdx.z * Mrows + row) * TWOE + col;
            *(float2*)p             = make_float2(acc[mt][nt][0], acc[mt][nt][1]);
            *(float2*)(p + 8*TWOE)  = make_float2(acc[mt][nt][2], acc[mt][nt][3]);
        }
}

// ---------------- reduce split-K partials + transpose ----------------
__global__ void __launch_bounds__(256) reduceT_k(
        const float* __restrict__ part, const float* __restrict__ W,
        float* __restrict__ outT, int nsplit, int combine)
{
    __shared__ float t[64][65];
    int n0 = blockIdx.x * 64, o0 = blockIdx.y * 64;
    int c0 = threadIdx.x & 63, r4 = threadIdx.x >> 6;
    #pragma unroll
    for (int p = 0; p < 16; p++) {
        int nl = p*4 + r4;
        float s = 0.f;
        for (int z = 0; z < nsplit; z++)
            s += part[((size_t)z*NI + n0 + nl)*TWOE + o0 + c0];
        t[nl][c0] = s;
    }
    __syncthreads();
    #pragma unroll
    for (int p = 0; p < 16; p++) {
        int ol = p*4 + r4;
        float v = t[c0][ol];
        if (combine) v = 0.5f*(v + W[(size_t)(o0+ol)*NI + n0 + c0]);
        outT[(size_t)(o0+ol)*NI + n0 + c0] = v;
    }
}

// ---------------- finalize h -> mu / logvar ----------------
__global__ void __launch_bounds__(128) hfinal_k(
        const float* __restrict__ part, int nchunks,
        const float* __restrict__ rnp, const float* __restrict__ bias,
        float* __restrict__ out_mu, float* __restrict__ out_lv)
{
    __shared__ float sq[64];
    __shared__ float sinv, s_rn;
    int kb = blockIdx.x, o = threadIdx.x;
    if (o == 0) {
        float t = 0.f;
        #pragma unroll
        for (int c = 0; c < 8; c++) t += rnp[kb*8 + c];
        s_rn = 1.0f / fmaxf(sqrtf(t), 1e-12f);
    }
    float s = 0.f;
    for (int c = 0; c < nchunks; c++) s += part[(size_t)c*512*TWOE + (size_t)kb*TWOE + o];
    __syncthreads();
    float h = s * s_rn + bias[o];
    if (o < 64) sq[o] = h*h;
    __syncthreads();
    if (o == 0) {
        float t = 0.f;
        #pragma unroll
        for (int i = 0; i < 64; i++) t += sq[i];
        sinv = 1.0f / fmaxf(sqrtf(t), 1e-12f);
    }
    __syncthreads();
    if (o < 64) out_mu[(size_t)kb*EE + o] = h * sinv;
    else        out_lv[(size_t)kb*EE + (o-64)] = -h;
}

// ---------------- decoder ----------------
__global__ void __launch_bounds__(256) decoder_k(
        const float* __restrict__ items, const float* __restrict__ cates,
        const float* __restrict__ mu, float* __restrict__ out, int N)
{
    __shared__ float itemsT[64][68];
    __shared__ float mu_s[16][64][4];
    __shared__ float cs[64][4];
    int tid = threadIdx.x;
    int tx = tid & 15, ty = tid >> 4;
    int n0 = blockIdx.x * 64;
    int bt = blockIdx.y * 16;
    #pragma unroll
    for (int i = 0; i < 16; i++) {
        int idx = tid + i*256;
        int n = idx >> 6, e = idx & 63;
        itemsT[e][n] = items[(size_t)(n0+n)*EE + e];
    }
    #pragma unroll
    for (int i = 0; i < 16; i++) {
        int idx = tid + i*256;
        int kb = idx >> 6, e = idx & 63;
        int k = kb >> 4, b = kb & 15;
        mu_s[b][e][k] = mu[(size_t)(k*BB + bt + b)*EE + e];
    }
    {
        int n = tid >> 2, kk = tid & 3;
        cs[n][kk] = cates[(size_t)(n0+n)*KP + kk];
    }
    __syncthreads();

    float acc[4][KP];
    #pragma unroll
    for (int i = 0; i < 4; i++)
        #pragma unroll
        for (int k = 0; k < KP; k++) acc[i][k] = 0.f;

    #pragma unroll 4
    for (int e = 0; e < 64; e++) {
        float4 a = *(const float4*)&itemsT[e][tx*4];
        float4 mm = *(const float4*)&mu_s[ty][e][0];
        float aw[4] = {a.x, a.y, a.z, a.w};
        #pragma unroll
        for (int i = 0; i < 4; i++) {
            acc[i][0] += aw[i]*mm.x; acc[i][1] += aw[i]*mm.y;
            acc[i][2] += aw[i]*mm.z; acc[i][3] += aw[i]*mm.w;
        }
    }
    int b = bt + ty;
    #pragma unroll
    for (int i = 0; i < 4; i++) {
        int nl = tx*4 + i;
        float4 c = *(const float4*)&cs[nl][0];
        float p = __expf(acc[i][0])*c.x + __expf(acc[i][1])*c.y
                + __expf(acc[i][2])*c.z + __expf(acc[i][3])*c.w;
        out[(size_t)b*N + n0 + nl] = __logf(p);
    }
}

// ---------------- launch ----------------
extern "C" void kernel_launch(void* const* d_in, const int* in_sizes, int n_in,
                              void* d_out, int out_size)
{
    const float* x_cf    = (const float*)d_in[0];
    const float* x_tx    = (const float*)d_in[1];
    const float* adj     = (const float*)d_in[2];
    const float* cf_emb  = (const float*)d_in[3];
    const float* cf_prot = (const float*)d_in[4];
    const float* cf_W    = (const float*)d_in[5];
    const float* cf_b    = (const float*)d_in[6];
    const float* tx_emb  = (const float*)d_in[7];
    const float* tx_prot = (const float*)d_in[8];
    const float* tx_W    = (const float*)d_in[9];
    const float* tx_b    = (const float*)d_in[10];
    float* out = (float*)d_out;

    float *p_protos_cf, *p_protos_tx, *p_items_cf, *p_items_tx;
    float *p_cates_cf, *p_cates_tx, *p_ctT_cf, *p_ctT_tx, *p_rnp_cf, *p_rnp_tx;
    float *p_P1T, *p_MT, *p_big, *p_part_cf, *p_part_tx;
    cudaGetSymbolAddress((void**)&p_protos_cf, g_protos_cf);
    cudaGetSymbolAddress((void**)&p_protos_tx, g_protos_tx);
    cudaGetSymbolAddress((void**)&p_items_cf,  g_items_cf);
    cudaGetSymbolAddress((void**)&p_items_tx,  g_items_tx);
    cudaGetSymbolAddress((void**)&p_cates_cf,  g_cates_cf);
    cudaGetSymbolAddress((void**)&p_cates_tx,  g_cates_tx);
    cudaGetSymbolAddress((void**)&p_ctT_cf,    g_ctT_cf);
    cudaGetSymbolAddress((void**)&p_ctT_tx,    g_ctT_tx);
    cudaGetSymbolAddress((void**)&p_rnp_cf,    g_rnp_cf);
    cudaGetSymbolAddress((void**)&p_rnp_tx,    g_rnp_tx);
    cudaGetSymbolAddress((void**)&p_P1T,       g_P1T);
    cudaGetSymbolAddress((void**)&p_MT,        g_MT);
    cudaGetSymbolAddress((void**)&p_big,       g_bigpart);
    cudaGetSymbolAddress((void**)&p_part_cf,   g_part_cf);
    cudaGetSymbolAddress((void**)&p_part_tx,   g_part_tx);

    static cudaStream_t s_tx = nullptr, s_pre = nullptr;
    static cudaEvent_t ev_fork = nullptr, ev_tx = nullptr, ev_pre = nullptr;
    if (!s_tx) {
        cudaStreamCreateWithFlags(&s_tx,  cudaStreamNonBlocking);
        cudaStreamCreateWithFlags(&s_pre, cudaStreamNonBlocking);
        cudaEventCreateWithFlags(&ev_fork, cudaEventDisableTiming);
        cudaEventCreateWithFlags(&ev_tx,   cudaEventDisableTiming);
        cudaEventCreateWithFlags(&ev_pre,  cudaEventDisableTiming);
        cudaFuncSetAttribute(mma_gemm_k,
            cudaFuncAttributeMaxDynamicSharedMemorySize, SMEM_GEMM);
    }

    // ---- stem ----
    proto_norm_k<<<1, 256>>>(cf_prot, tx_prot);
    cudaEventRecord(ev_fork, 0);
    cudaStreamWaitEvent(s_tx,  ev_fork, 0);
    cudaStreamWaitEvent(s_pre, ev_fork, 0);

    // ---- text branch on s_tx ----
    items_cates_k<<<NW/8, 256, 0, s_tx>>>(tx_emb, p_protos_tx, p_items_tx, p_cates_tx, p_ctT_tx, NW);
    rnormp_k<<<dim3(BB, 8), 256, 0, s_tx>>>(x_tx, p_cates_tx, p_rnp_tx, NW);
    mma_gemm_k<<<dim3(4, 1, HSPLIT), 256, SMEM_GEMM, s_tx>>>(
        x_tx, p_ctT_tx, tx_W, p_part_tx, 512, NW, NW/HSPLIT, 1);
    hfinal_k<<<KP*BB, 128, 0, s_tx>>>(p_part_tx, HSPLIT, p_rnp_tx, tx_b,
                                      out + OUT_TXMU, out + OUT_TXLV);
    decoder_k<<<dim3(NW/64, BB/16), 256, 0, s_tx>>>(p_items_tx, p_cates_tx,
                                                    out + OUT_TXMU, out + OUT_TEXT, NW);
    cudaEventRecord(ev_tx, s_tx);

    // ---- cf prep on s_pre ----
    items_cates_k<<<NI/8, 256, 0, s_pre>>>(cf_emb, p_protos_cf, p_items_cf, p_cates_cf, p_ctT_cf, NI);
    rnormp_k<<<dim3(BB, 8), 256, 0, s_pre>>>(x_cf, p_cates_cf, p_rnp_cf, NI);
    cudaEventRecord(ev_pre, s_pre);

    // ---- adjacency chain ----
    // P1 = adj @ cf_W^T  -> P1T
    mma_gemm_k<<<dim3(NI/128, 1, ASPLIT), 256, SMEM_GEMM>>>(
        adj, nullptr, cf_W, p_big, NI, NI, NI/ASPLIT, 0);
    reduceT_k<<<dim3(NI/64, 2), 256>>>(p_big, nullptr, p_P1T, ASPLIT, 0);
    // P2 = adj @ P1 -> MT = 0.5*(P2T + W)
    mma_gemm_k<<<dim3(NI/128, 1, ASPLIT), 256, SMEM_GEMM>>>(
        adj, nullptr, p_P1T, p_big, NI, NI, NI/ASPLIT, 0);
    reduceT_k<<<dim3(NI/64, 2), 256>>>(p_big, cf_W, p_MT, ASPLIT, 1);

    // hpart_cf
    cudaStreamWaitEvent(0, ev_pre, 0);
    mma_gemm_k<<<dim3(4, 1, HSPLIT), 256, SMEM_GEMM>>>(
        x_cf, p_ctT_cf, p_MT, p_part_cf, 512, NI, NI/HSPLIT, 1);
    hfinal_k<<<KP*BB, 128>>>(p_part_cf, HSPLIT, p_rnp_cf, cf_b,
                             out + OUT_CFMU, out + OUT_CFLV);
    decoder_k<<<dim3(NI/64, BB/16), 256>>>(p_items_cf, p_cates_cf,
                                           out + OUT_CFMU, out + OUT_RATING, NI);

    cudaStreamWaitEvent(0, ev_tx, 0);
}

// round 9
// speedup vs baseline: 1.2286x; 1.1476x over previous
#include <cuda_runtime.h>
#include <math.h>
#include <stdint.h>

// ---------------- problem constants ----------------
#define BB    128
#define NI    8192
#define NW    16384
#define EE    64
#define KP    4
#define TWOE  128

#define OUT_RATING  0
#define OUT_TEXT    (128*8192)
#define OUT_CFMU    (OUT_TEXT + 128*16384)
#define OUT_CFLV    (OUT_CFMU + 4*128*64)
#define OUT_TXMU    (OUT_CFLV + 4*128*64)
#define OUT_TXLV    (OUT_TXMU + 4*128*64)

#define HSPLIT 64
#define ASPLIT 8

// mma tile config (128x128), A double-buffered, B triple-buffered (cp.async)
#define BLKK   32
#define S_LD   36
#define TBUF_B (128*S_LD*4)                 // 18432 bytes per buffer
#define SMEM_GEMM (5*TBUF_B)                // 2 A + 3 B = 92160

// ---------------- scratch ----------------
__device__ float g_protos_cf[KP*EE];
__device__ float g_protos_tx[KP*EE];
__device__ float g_items_cf[NI*EE];
__device__ float g_items_tx[NW*EE];
__device__ float g_cates_cf[NI*KP];
__device__ float g_cates_tx[NW*KP];
__device__ float g_ctT_cf[KP*NI];
__device__ float g_ctT_tx[KP*NW];
__device__ float g_rnp_cf[KP*BB*8];
__device__ float g_rnp_tx[KP*BB*8];
__device__ float g_P1T[TWOE*NI];            // tf32 bits
__device__ float g_MT [TWOE*NI];            // tf32 bits
__device__ float g_WC [TWOE*NI];            // cf_W converted to tf32 bits
__device__ float g_WTC[TWOE*NW];            // tx_W converted to tf32 bits
__device__ float g_bigpart[8*NI*TWOE];
__device__ float g_part_cf[HSPLIT*512*TWOE];
__device__ float g_part_tx[HSPLIT*512*TWOE];

// ---------------- TF32 helpers ----------------
__device__ __forceinline__ uint32_t f2tf(float f) {
    uint32_t r;
    asm("cvt.rna.tf32.f32 %0, %1;" : "=r"(r) : "f"(f));
    return r;
}
__device__ __forceinline__ void mma_tf32(float c[4], const uint32_t a[4],
                                         uint32_t b0, uint32_t b1) {
    asm volatile(
        "mma.sync.aligned.m16n8k8.row.col.f32.tf32.tf32.f32 "
        "{%0,%1,%2,%3}, {%4,%5,%6,%7}, {%8,%9}, {%0,%1,%2,%3};"
        : "+f"(c[0]), "+f"(c[1]), "+f"(c[2]), "+f"(c[3])
        : "r"(a[0]), "r"(a[1]), "r"(a[2]), "r"(a[3]), "r"(b0), "r"(b1));
}
__device__ __forceinline__ void ldsm4(uint32_t& r0, uint32_t& r1,
                                      uint32_t& r2, uint32_t& r3, uint32_t addr) {
    asm volatile("ldmatrix.sync.aligned.m8n8.x4.shared.b16 {%0,%1,%2,%3}, [%4];"
                 : "=r"(r0), "=r"(r1), "=r"(r2), "=r"(r3) : "r"(addr));
}

// ---------------- k0: normalize prototypes ----------------
__global__ void proto_norm_k(const float* __restrict__ cfp, const float* __restrict__ txp) {
    int tid = threadIdx.x;
    int w = tid >> 5, lane = tid & 31;
    const float* src = (w < 4) ? cfp : txp;
    float* dst = (w < 4) ? g_protos_cf : g_protos_tx;
    int row = w & 3;
    float v0 = src[row*EE + lane];
    float v1 = src[row*EE + 32 + lane];
    float s = v0*v0 + v1*v1;
    #pragma unroll
    for (int off = 16; off; off >>= 1) s += __shfl_xor_sync(0xffffffffu, s, off);
    float inv = 1.0f / fmaxf(sqrtf(s), 1e-12f);
    dst[row*EE + lane]      = v0 * inv;
    dst[row*EE + 32 + lane] = v1 * inv;
}

// ---------------- convert W rows to tf32 bits ----------------
__global__ void __launch_bounds__(256) convW_k(const float4* __restrict__ in,
                                              uint4* __restrict__ out) {
    int i = blockIdx.x * 256 + threadIdx.x;
    float4 v = in[i];
    out[i] = make_uint4(f2tf(v.x), f2tf(v.y), f2tf(v.z), f2tf(v.w));
}

// ---------------- k1: item norm + cates softmax (+ transposed) ----------------
__global__ void __launch_bounds__(256) items_cates_k(
        const float* __restrict__ emb, const float* __restrict__ protos_g,
        float* __restrict__ items_out, float* __restrict__ cates_out,
        float* __restrict__ catesT_out, int N)
{
    __shared__ float ps[KP*EE];
    int tid = threadIdx.x;
    ps[tid] = protos_g[tid];
    __syncthreads();
    int w = tid >> 5, lane = tid & 31;
    int n = blockIdx.x * 8 + w;
    if (n >= N) return;
    float v0 = emb[n*EE + lane];
    float v1 = emb[n*EE + 32 + lane];
    float s = v0*v0 + v1*v1;
    #pragma unroll
    for (int off = 16; off; off >>= 1) s += __shfl_xor_sync(0xffffffffu, s, off);
    float inv = 1.0f / fmaxf(sqrtf(s), 1e-12f);
    float h0 = v0 * inv, h1 = v1 * inv;
    items_out[n*EE + lane]      = h0;
    items_out[n*EE + 32 + lane] = h1;
    float d[KP];
    #pragma unroll
    for (int k = 0; k < KP; k++) {
        float dk = h0 * ps[k*EE + lane] + h1 * ps[k*EE + 32 + lane];
        #pragma unroll
        for (int off = 16; off; off >>= 1) dk += __shfl_xor_sync(0xffffffffu, dk, off);
        d[k] = dk;
    }
    if (lane == 0) {
        float m = fmaxf(fmaxf(d[0], d[1]), fmaxf(d[2], d[3]));
        float e0 = __expf(d[0]-m), e1 = __expf(d[1]-m), e2 = __expf(d[2]-m), e3 = __expf(d[3]-m);
        float is = 1.0f / (e0+e1+e2+e3);
        float c0 = e0*is, c1 = e1*is, c2 = e2*is, c3 = e3*is;
        *(float4*)&cates_out[n*KP] = make_float4(c0, c1, c2, c3);
        catesT_out[0*N + n] = c0;
        catesT_out[1*N + n] = c1;
        catesT_out[2*N + n] = c2;
        catesT_out[3*N + n] = c3;
    }
}

// ---------------- k2: rnorm partials ----------------
__global__ void __launch_bounds__(256) rnormp_k(
        const float* __restrict__ x, const float* __restrict__ cates,
        float* __restrict__ rnp, int N)
{
    __shared__ float red[8][KP];
    int b = blockIdx.x, chunk = blockIdx.y, tid = threadIdx.x;
    int n0 = chunk * (N >> 3), n1 = n0 + (N >> 3);
    float s0=0.f, s1=0.f, s2=0.f, s3=0.f;
    const float* xr = x + (size_t)b * N;
    for (int n = n0 + tid; n < n1; n += 256) {
        float xv = xr[n];
        float4 c = *(const float4*)&cates[n*KP];
        float t0 = xv*c.x, t1 = xv*c.y, t2 = xv*c.z, t3 = xv*c.w;
        s0 += t0*t0; s1 += t1*t1; s2 += t2*t2; s3 += t3*t3;
    }
    #pragma unroll
    for (int off = 16; off; off >>= 1) {
        s0 += __shfl_xor_sync(0xffffffffu, s0, off);
        s1 += __shfl_xor_sync(0xffffffffu, s1, off);
        s2 += __shfl_xor_sync(0xffffffffu, s2, off);
        s3 += __shfl_xor_sync(0xffffffffu, s3, off);
    }
    int w = tid >> 5;
    if ((tid & 31) == 0) { red[w][0]=s0; red[w][1]=s1; red[w][2]=s2; red[w][3]=s3; }
    __syncthreads();
    if (tid < KP) {
        float t = 0.f;
        #pragma unroll
        for (int i = 0; i < 8; i++) t += red[i][tid];
        rnp[(tid*BB + b)*8 + chunk] = t;
    }
}

// ---------------- TF32 MMA GEMM: A staged (R5 path), B via cp.async (tf32 bits) ----
// A: amode 0: row-major [m][Ktot]; amode 1: Y[m][n]=x[m][n]*ctT[bx][n]
// B: rows [o][Ktot], ALREADY tf32 bits
// out: part[(bz*Mrows + row)*128 + o]
__global__ void __launch_bounds__(256, 2) mma_gemm_k(
        const float* __restrict__ A, const float* __restrict__ ctT,
        const float* __restrict__ B, float* __restrict__ part,
        int Mrows, int Ktot, int Ksplit, int amode)
{
    extern __shared__ uint32_t usmem[];
    uint32_t* Asm = usmem;                    // [2][128][S_LD]
    int tid = threadIdx.x;
    int lane = tid & 31, w = tid >> 5;
    int wm = w & 3, wn = w >> 2;
    int lr = lane >> 2, lc = lane & 3;
    int m0 = blockIdx.x * 128;
    int kc0 = blockIdx.z * Ksplit;
    int niter = Ksplit / BLKK;
    const float* ctb = amode ? (ctT + (size_t)blockIdx.x * Ktot) : (const float*)0;

    uint32_t as_base = (uint32_t)__cvta_generic_to_shared(Asm);
    uint32_t bs_base = as_base + 2*TBUF_B;    // B buffers follow A's
    int sel = lane >> 3, lr8 = lane & 7;
    uint32_t a_off = ((wm*32 + (sel&1)*8 + lr8)*S_LD + (sel>>1)*4) * 4;
    uint32_t b_off = ((wn*64 + (sel>>1)*8 + lr8)*S_LD + (sel&1)*4) * 4;

    float acc[2][8][4];
    #pragma unroll
    for (int mt = 0; mt < 2; mt++)
        #pragma unroll
        for (int nt = 0; nt < 8; nt++)
            #pragma unroll
            for (int i = 0; i < 4; i++) acc[mt][nt][i] = 0.f;

    float4 ra[4];
    int bo = tid >> 1, bk0 = (tid & 1) * 16;  // B copy coords (R5 pattern)

    auto ldA = [&](int kc) {
        #pragma unroll
        for (int i = 0; i < 4; i++) {
            int lin = tid + i*256;
            int mm = lin >> 3, kk = (lin & 7) * 4;
            if (amode == 0) {
                ra[i] = *(const float4*)(A + (size_t)(m0 + mm) * Ktot + kc + kk);
            } else {
                float4 v = *(const float4*)(A + (size_t)mm * Ktot + kc + kk);
                float4 c = *(const float4*)(ctb + kc + kk);
                v.x *= c.x; v.y *= c.y; v.z *= c.z; v.w *= c.w;
                ra[i] = v;
            }
        }
    };
    auto stA = [&](int buf) {
        uint32_t* base = Asm + buf*128*S_LD;
        #pragma unroll
        for (int i = 0; i < 4; i++) {
            int lin = tid + i*256;
            int mm = lin >> 3, kk = (lin & 7) * 4;
            uint4 u;
            u.x = f2tf(ra[i].x); u.y = f2tf(ra[i].y);
            u.z = f2tf(ra[i].z); u.w = f2tf(ra[i].w);
            *(uint4*)(base + mm*S_LD + kk) = u;
        }
    };
    auto issueB = [&](int bbuf, int kc) {
        uint32_t dbase = bs_base + (uint32_t)bbuf*TBUF_B + (uint32_t)(bo*S_LD + bk0)*4;
        const float* sbase = B + (size_t)bo * Ktot + kc + bk0;
        #pragma unroll
        for (int i = 0; i < 4; i++) {
            asm volatile("cp.async.cg.shared.global [%0], [%1], 16;"
                         :: "r"(dbase + i*16), "l"(sbase + i*4) : "memory");
        }
        asm volatile("cp.async.commit_group;" ::: "memory");
    };
    auto compute = [&](int abuf, int bbuf) {
        uint32_t abase = as_base + abuf*TBUF_B + a_off;
        uint32_t bbase = bs_base + bbuf*TBUF_B + b_off;
        #pragma unroll
        for (int ks = 0; ks < 4; ks++) {
            int k0b = ks * 8 * 4;
            uint32_t afr[2][4];
            #pragma unroll
            for (int mt = 0; mt < 2; mt++)
                ldsm4(afr[mt][0], afr[mt][1], afr[mt][2], afr[mt][3],
                      abase + mt*(16*S_LD*4) + k0b);
            #pragma unroll
            for (int np = 0; np < 4; np++) {
                uint32_t b0, b1, b2, b3;
                ldsm4(b0, b1, b2, b3, bbase + np*(16*S_LD*4) + k0b);
                mma_tf32(acc[0][2*np  ], afr[0], b0, b1);
                mma_tf32(acc[1][2*np  ], afr[1], b0, b1);
                mma_tf32(acc[0][2*np+1], afr[0], b2, b3);
                mma_tf32(acc[1][2*np+1], afr[1], b2, b3);
            }
        }
    };

    // prologue: A tile0 -> smem, A tile1 -> regs; B groups 0,1 in flight
    ldA(kc0);
    issueB(0, kc0);
    issueB(1, kc0 + BLKK);
    stA(0);
    ldA(kc0 + BLKK);
    asm volatile("cp.async.wait_group 1;" ::: "memory");
    __syncthreads();

    int bcur = 0;
    for (int it = 0; it < niter; it++) {
        int acur = it & 1;
        compute(acur, bcur);
        if (it + 1 < niter) {
            stA(1 - acur);                       // A tile it+1 -> smem
            if (it + 2 < niter) {
                ldA(kc0 + (it+2)*BLKK);          // A tile it+2 -> regs
                int bnext = bcur + 2; if (bnext >= 3) bnext -= 3;
                issueB(bnext, kc0 + (it+2)*BLKK);
                asm volatile("cp.async.wait_group 1;" ::: "memory");
            } else {
                asm volatile("cp.async.wait_group 0;" ::: "memory");
            }
        }
        __syncthreads();
        if (++bcur == 3) bcur = 0;
    }

    #pragma unroll
    for (int mt = 0; mt < 2; mt++)
        #pragma unroll
        for (int nt = 0; nt < 8; nt++) {
            int row = m0 + wm*32 + mt*16 + lr;
            int col = wn*64 + nt*8 + lc*2;
            float* p = part + ((size_t)blockIdx.z * Mrows + row) * TWOE + col;
            *(float2*)p             = make_float2(acc[mt][nt][0], acc[mt][nt][1]);
            *(float2*)(p + 8*TWOE)  = make_float2(acc[mt][nt][2], acc[mt][nt][3]);
        }
}

// ---------------- reduce split-K partials + transpose, emit tf32 bits ----------
__global__ void __launch_bounds__(256) reduceT_k(
        const float* __restrict__ part, const float* __restrict__ W,
        float* __restrict__ outT, int combine)
{
    __shared__ float t[64][65];
    int n0 = blockIdx.x * 64, o0 = blockIdx.y * 64;
    int c0 = threadIdx.x & 63, r4 = threadIdx.x >> 6;
    #pragma unroll
    for (int p = 0; p < 16; p++) {
        int nl = p*4 + r4;
        float s = 0.f;
        #pragma unroll
        for (int z = 0; z < ASPLIT; z++)
            s += part[((size_t)z*NI + n0 + nl)*TWOE + o0 + c0];
        t[nl][c0] = s;
    }
    __syncthreads();
    #pragma unroll
    for (int p = 0; p < 16; p++) {
        int ol = p*4 + r4;
        float v = t[c0][ol];
        if (combine) v = 0.5f*(v + W[(size_t)(o0+ol)*NI + n0 + c0]);
        outT[(size_t)(o0+ol)*NI + n0 + c0] = __uint_as_float(f2tf(v));
    }
}

// ---------------- finalize h -> mu / logvar ----------------
__global__ void __launch_bounds__(128) hfinal_k(
        const float* __restrict__ part, int nchunks,
        const float* __restrict__ rnp, const float* __restrict__ bias,
        float* __restrict__ out_mu, float* __restrict__ out_lv)
{
    __shared__ float sq[64];
    __shared__ float sinv, s_rn;
    int kb = blockIdx.x, o = threadIdx.x;
    if (o == 0) {
        float t = 0.f;
        #pragma unroll
        for (int c = 0; c < 8; c++) t += rnp[kb*8 + c];
        s_rn = 1.0f / fmaxf(sqrtf(t), 1e-12f);
    }
    float s = 0.f;
    for (int c = 0; c < nchunks; c++) s += part[(size_t)c*512*TWOE + (size_t)kb*TWOE + o];
    __syncthreads();
    float h = s * s_rn + bias[o];
    if (o < 64) sq[o] = h*h;
    __syncthreads();
    if (o == 0) {
        float t = 0.f;
        #pragma unroll
        for (int i = 0; i < 64; i++) t += sq[i];
        sinv = 1.0f / fmaxf(sqrtf(t), 1e-12f);
    }
    __syncthreads();
    if (o < 64) out_mu[(size_t)kb*EE + o] = h * sinv;
    else        out_lv[(size_t)kb*EE + (o-64)] = -h;
}

// ---------------- decoder ----------------
__global__ void __launch_bounds__(256) decoder_k(
        const float* __restrict__ items, const float* __restrict__ cates,
        const float* __restrict__ mu, float* __restrict__ out, int N)
{
    __shared__ float itemsT[64][68];
    __shared__ float mu_s[16][64][4];
    __shared__ float cs[64][4];
    int tid = threadIdx.x;
    int tx = tid & 15, ty = tid >> 4;
    int n0 = blockIdx.x * 64;
    int bt = blockIdx.y * 16;
    #pragma unroll
    for (int i = 0; i < 16; i++) {
        int idx = tid + i*256;
        int n = idx >> 6, e = idx & 63;
        itemsT[e][n] = items[(size_t)(n0+n)*EE + e];
    }
    #pragma unroll
    for (int i = 0; i < 16; i++) {
        int idx = tid + i*256;
        int kb = idx >> 6, e = idx & 63;
        int k = kb >> 4, b = kb & 15;
        mu_s[b][e][k] = mu[(size_t)(k*BB + bt + b)*EE + e];
    }
    {
        int n = tid >> 2, kk = tid & 3;
        cs[n][kk] = cates[(size_t)(n0+n)*KP + kk];
    }
    __syncthreads();

    float acc[4][KP];
    #pragma unroll
    for (int i = 0; i < 4; i++)
        #pragma unroll
        for (int k = 0; k < KP; k++) acc[i][k] = 0.f;

    #pragma unroll 4
    for (int e = 0; e < 64; e++) {
        float4 a = *(const float4*)&itemsT[e][tx*4];
        float4 mm = *(const float4*)&mu_s[ty][e][0];
        float aw[4] = {a.x, a.y, a.z, a.w};
        #pragma unroll
        for (int i = 0; i < 4; i++) {
            acc[i][0] += aw[i]*mm.x; acc[i][1] += aw[i]*mm.y;
            acc[i][2] += aw[i]*mm.z; acc[i][3] += aw[i]*mm.w;
        }
    }
    int b = bt + ty;
    #pragma unroll
    for (int i = 0; i < 4; i++) {
        int nl = tx*4 + i;
        float4 c = *(const float4*)&cs[nl][0];
        float p = __expf(acc[i][0])*c.x + __expf(acc[i][1])*c.y
                + __expf(acc[i][2])*c.z + __expf(acc[i][3])*c.w;
        out[(size_t)b*N + n0 + nl] = __logf(p);
    }
}

// ---------------- launch ----------------
extern "C" void kernel_launch(void* const* d_in, const int* in_sizes, int n_in,
                              void* d_out, int out_size)
{
    const float* x_cf    = (const float*)d_in[0];
    const float* x_tx    = (const float*)d_in[1];
    const float* adj     = (const float*)d_in[2];
    const float* cf_emb  = (const float*)d_in[3];
    const float* cf_prot = (const float*)d_in[4];
    const float* cf_W    = (const float*)d_in[5];
    const float* cf_b    = (const float*)d_in[6];
    const float* tx_emb  = (const float*)d_in[7];
    const float* tx_prot = (const float*)d_in[8];
    const float* tx_W    = (const float*)d_in[9];
    const float* tx_b    = (const float*)d_in[10];
    float* out = (float*)d_out;

    float *p_protos_cf, *p_protos_tx, *p_items_cf, *p_items_tx;
    float *p_cates_cf, *p_cates_tx, *p_ctT_cf, *p_ctT_tx, *p_rnp_cf, *p_rnp_tx;
    float *p_P1T, *p_MT, *p_WC, *p_WTC, *p_big, *p_part_cf, *p_part_tx;
    cudaGetSymbolAddress((void**)&p_protos_cf, g_protos_cf);
    cudaGetSymbolAddress((void**)&p_protos_tx, g_protos_tx);
    cudaGetSymbolAddress((void**)&p_items_cf,  g_items_cf);
    cudaGetSymbolAddress((void**)&p_items_tx,  g_items_tx);
    cudaGetSymbolAddress((void**)&p_cates_cf,  g_cates_cf);
    cudaGetSymbolAddress((void**)&p_cates_tx,  g_cates_tx);
    cudaGetSymbolAddress((void**)&p_ctT_cf,    g_ctT_cf);
    cudaGetSymbolAddress((void**)&p_ctT_tx,    g_ctT_tx);
    cudaGetSymbolAddress((void**)&p_rnp_cf,    g_rnp_cf);
    cudaGetSymbolAddress((void**)&p_rnp_tx,    g_rnp_tx);
    cudaGetSymbolAddress((void**)&p_P1T,       g_P1T);
    cudaGetSymbolAddress((void**)&p_MT,        g_MT);
    cudaGetSymbolAddress((void**)&p_WC,        g_WC);
    cudaGetSymbolAddress((void**)&p_WTC,       g_WTC);
    cudaGetSymbolAddress((void**)&p_big,       g_bigpart);
    cudaGetSymbolAddress((void**)&p_part_cf,   g_part_cf);
    cudaGetSymbolAddress((void**)&p_part_tx,   g_part_tx);

    static cudaStream_t s_tx = nullptr, s_pre = nullptr;
    static cudaEvent_t ev_fork = nullptr, ev_tx = nullptr, ev_pre = nullptr;
    if (!s_tx) {
        cudaStreamCreateWithFlags(&s_tx,  cudaStreamNonBlocking);
        cudaStreamCreateWithFlags(&s_pre, cudaStreamNonBlocking);
        cudaEventCreateWithFlags(&ev_fork, cudaEventDisableTiming);
        cudaEventCreateWithFlags(&ev_tx,   cudaEventDisableTiming);
        cudaEventCreateWithFlags(&ev_pre,  cudaEventDisableTiming);
        cudaFuncSetAttribute(mma_gemm_k,
            cudaFuncAttributeMaxDynamicSharedMemorySize, SMEM_GEMM);
    }

    // ---- stem ----
    proto_norm_k<<<1, 256>>>(cf_prot, tx_prot);
    cudaEventRecord(ev_fork, 0);
    cudaStreamWaitEvent(s_tx,  ev_fork, 0);
    cudaStreamWaitEvent(s_pre, ev_fork, 0);

    // ---- text branch on s_tx ----
    convW_k<<<TWOE*NW/4/256, 256, 0, s_tx>>>((const float4*)tx_W, (uint4*)p_WTC);
    items_cates_k<<<NW/8, 256, 0, s_tx>>>(tx_emb, p_protos_tx, p_items_tx, p_cates_tx, p_ctT_tx, NW);
    rnormp_k<<<dim3(BB, 8), 256, 0, s_tx>>>(x_tx, p_cates_tx, p_rnp_tx, NW);
    mma_gemm_k<<<dim3(4, 1, HSPLIT), 256, SMEM_GEMM, s_tx>>>(
        x_tx, p_ctT_tx, p_WTC, p_part_tx, 512, NW, NW/HSPLIT, 1);
    hfinal_k<<<KP*BB, 128, 0, s_tx>>>(p_part_tx, HSPLIT, p_rnp_tx, tx_b,
                                      out + OUT_TXMU, out + OUT_TXLV);
    decoder_k<<<dim3(NW/64, BB/16), 256, 0, s_tx>>>(p_items_tx, p_cates_tx,
                                                    out + OUT_TXMU, out + OUT_TEXT, NW);
    cudaEventRecord(ev_tx, s_tx);

    // ---- cf prep on s_pre ----
    items_cates_k<<<NI/8, 256, 0, s_pre>>>(cf_emb, p_protos_cf, p_items_cf, p_cates_cf, p_ctT_cf, NI);
    rnormp_k<<<dim3(BB, 8), 256, 0, s_pre>>>(x_cf, p_cates_cf, p_rnp_cf, NI);
    cudaEventRecord(ev_pre, s_pre);

    // ---- adjacency chain ----
    convW_k<<<TWOE*NI/4/256, 256>>>((const float4*)cf_W, (uint4*)p_WC);
    // P1 = adj @ cf_W^T  -> P1T (tf32 bits)
    mma_gemm_k<<<dim3(NI/128, 1, ASPLIT), 256, SMEM_GEMM>>>(
        adj, nullptr, p_WC, p_big, NI, NI, NI/ASPLIT, 0);
    reduceT_k<<<dim3(NI/64, 2), 256>>>(p_big, nullptr, p_P1T, 0);
    // P2 = adj @ P1 -> MT = 0.5*(P2T + W) (tf32 bits)
    mma_gemm_k<<<dim3(NI/128, 1, ASPLIT), 256, SMEM_GEMM>>>(
        adj, nullptr, p_P1T, p_big, NI, NI, NI/ASPLIT, 0);
    reduceT_k<<<dim3(NI/64, 2), 256>>>(p_big, cf_W, p_MT, 1);

    // hpart_cf
    cudaStreamWaitEvent(0, ev_pre, 0);
    mma_gemm_k<<<dim3(4, 1, HSPLIT), 256, SMEM_GEMM>>>(
        x_cf, p_ctT_cf, p_MT, p_part_cf, 512, NI, NI/HSPLIT, 1);
    hfinal_k<<<KP*BB, 128>>>(p_part_cf, HSPLIT, p_rnp_cf, cf_b,
                             out + OUT_CFMU, out + OUT_CFLV);
    decoder_k<<<dim3(NI/64, BB/16), 256>>>(p_items_cf, p_cates_cf,
                                           out + OUT_CFMU, out + OUT_RATING, NI);

    cudaStreamWaitEvent(0, ev_tx, 0);
}